// round 1
// baseline (speedup 1.0000x reference)
#include <cuda_runtime.h>
#include <cstdint>

// Problem geometry (fixed by the dataset): 2 inputs of (8,1,1024,1024) fp32.
#define HH 1024
#define WW 1024
#define NB 8
#define PLANE (HH*WW)
#define NTOT (NB*PLANE)

// ---------------------------------------------------------------------------
// Scratch planes (device globals: allocation-free per harness rules)
// ---------------------------------------------------------------------------
static __device__ float g_isig[NTOT];                       // gauss7(I), reused pred then target
static __device__ float g_J11p[NTOT], g_J22p[NTOT], g_gJp[NTOT];
static __device__ float g_J11t[NTOT], g_J22t[NTOT], g_gJt[NTOT];
static __device__ double g_acc;

// ---------------------------------------------------------------------------
// Gaussian weights (match numpy: exp(-d^2/(2 sigma^2)) normalized)
// sigma=1.0 -> 7 taps, rho=0.5 -> 5 taps
// ---------------------------------------------------------------------------
#define E05f 0.6065306597126334f     /* exp(-0.5) */
#define E20f 0.1353352832366127f     /* exp(-2)   */
#define E45f 0.011108996538242306f   /* exp(-4.5) */
#define E80f 0.00033546262790251185f /* exp(-8)   */

__constant__ float cG7[7] = {
    E45f/(1.f+2.f*(E05f+E20f+E45f)),
    E20f/(1.f+2.f*(E05f+E20f+E45f)),
    E05f/(1.f+2.f*(E05f+E20f+E45f)),
    1.f /(1.f+2.f*(E05f+E20f+E45f)),
    E05f/(1.f+2.f*(E05f+E20f+E45f)),
    E20f/(1.f+2.f*(E05f+E20f+E45f)),
    E45f/(1.f+2.f*(E05f+E20f+E45f))
};
__constant__ float cG5[5] = {
    E80f/(1.f+2.f*(E20f+E80f)),
    E20f/(1.f+2.f*(E20f+E80f)),
    1.f /(1.f+2.f*(E20f+E80f)),
    E20f/(1.f+2.f*(E20f+E80f)),
    E80f/(1.f+2.f*(E20f+E80f))
};

// ---------------------------------------------------------------------------
// Sobel helpers (cross-correlation, matching XLA conv semantics)
// SOBEL_X = [[-1,0,1],[-2,0,2],[-1,0,1]]  SOBEL_Y = [[1,2,1],[0,0,0],[-1,-2,-1]]
// ---------------------------------------------------------------------------
__device__ __forceinline__ float sobx(const float* s, int st, int i, int j) {
    const float* a = s + (i-1)*st + j;
    const float* b = s + (i  )*st + j;
    const float* c = s + (i+1)*st + j;
    return (a[1]-a[-1]) + 2.f*(b[1]-b[-1]) + (c[1]-c[-1]);
}
__device__ __forceinline__ float soby(const float* s, int st, int i, int j) {
    const float* a = s + (i-1)*st + j;
    const float* c = s + (i+1)*st + j;
    return (a[-1]+2.f*a[0]+a[1]) - (c[-1]+2.f*c[0]+c[1]);
}

// ---------------------------------------------------------------------------
// K1: separable 7x7 Gaussian, zero padding.  tile 32x32, halo 3.
// ---------------------------------------------------------------------------
__global__ __launch_bounds__(1024) void k_gauss7(const float* __restrict__ in) {
    __shared__ float raw[38*40];
    __shared__ float hb[38*33];
    const int z  = blockIdx.z;
    const int r0 = blockIdx.y*32, c0 = blockIdx.x*32;
    const float* img = in + (size_t)z*PLANE;
    const int tid = threadIdx.y*32 + threadIdx.x;

    for (int idx = tid; idx < 38*38; idx += 1024) {
        int i = idx/38, j = idx - i*38;
        int gr = r0-3+i, gc = c0-3+j;
        float v = 0.f;
        if ((unsigned)gr < HH && (unsigned)gc < WW) v = img[gr*WW+gc];
        raw[i*40+j] = v;
    }
    __syncthreads();
    for (int idx = tid; idx < 38*32; idx += 1024) {
        int i = idx >> 5, j = idx & 31;
        const float* r = raw + i*40 + j;
        hb[i*33+j] = cG7[0]*r[0]+cG7[1]*r[1]+cG7[2]*r[2]+cG7[3]*r[3]
                    +cG7[4]*r[4]+cG7[5]*r[5]+cG7[6]*r[6];
    }
    __syncthreads();
    {
        const int ty = threadIdx.y, tx = threadIdx.x;
        const float* h = hb + ty*33 + tx;
        float a = cG7[0]*h[0]   + cG7[1]*h[33]  + cG7[2]*h[66] + cG7[3]*h[99]
                + cG7[4]*h[132] + cG7[5]*h[165] + cG7[6]*h[198];
        g_isig[(size_t)z*PLANE + (r0+ty)*WW + (c0+tx)] = a;
    }
}

// ---------------------------------------------------------------------------
// K2: from I_sigma compute J11 = gauss5(Isx^2), J22 = gauss5(Isy^2),
//     g_for_J = 1/(1 + (Isx^2+Isy^2+1e-6)/400).  tile 32x32, halo 3.
// ---------------------------------------------------------------------------
__global__ __launch_bounds__(1024) void k_struct(int which) {
    __shared__ float si [38*40];
    __shared__ float sqx[36*37], sqy[36*37];
    __shared__ float hx [36*33], hy [36*33];
    const int z  = blockIdx.z;
    const int r0 = blockIdx.y*32, c0 = blockIdx.x*32;
    const float* img = g_isig + (size_t)z*PLANE;
    float* J11 = (which ? g_J11t : g_J11p);
    float* J22 = (which ? g_J22t : g_J22p);
    float* gJ  = (which ? g_gJt  : g_gJp );
    const int tid = threadIdx.y*32 + threadIdx.x;

    for (int idx = tid; idx < 38*38; idx += 1024) {
        int i = idx/38, j = idx - i*38;
        int gr = r0-3+i, gc = c0-3+j;
        float v = 0.f;
        if ((unsigned)gr < HH && (unsigned)gc < WW) v = img[gr*WW+gc];
        si[i*40+j] = v;
    }
    __syncthreads();
    // Sobel of I_sigma squared, on 36x36 region (halo 2 for gauss5).
    // sq == 0 outside image domain (matches reference zero padding of product).
    for (int idx = tid; idx < 36*36; idx += 1024) {
        int i = idx/36, j = idx - i*36;
        int gr = r0-2+i, gc = c0-2+j;
        float vx = 0.f, vy = 0.f;
        if ((unsigned)gr < HH && (unsigned)gc < WW) {
            float sx = sobx(si, 40, i+1, j+1);
            float sy = soby(si, 40, i+1, j+1);
            vx = sx*sx; vy = sy*sy;
        }
        sqx[i*37+j] = vx; sqy[i*37+j] = vy;
    }
    __syncthreads();
    for (int idx = tid; idx < 36*32; idx += 1024) {
        int i = idx >> 5, j = idx & 31;
        const float* px = sqx + i*37 + j;
        const float* py = sqy + i*37 + j;
        hx[i*33+j] = cG5[0]*px[0]+cG5[1]*px[1]+cG5[2]*px[2]+cG5[3]*px[3]+cG5[4]*px[4];
        hy[i*33+j] = cG5[0]*py[0]+cG5[1]*py[1]+cG5[2]*py[2]+cG5[3]*py[3]+cG5[4]*py[4];
    }
    __syncthreads();
    {
        const int ty = threadIdx.y, tx = threadIdx.x;
        const float* px = hx + ty*33 + tx;
        const float* py = hy + ty*33 + tx;
        float a = cG5[0]*px[0]+cG5[1]*px[33]+cG5[2]*px[66]+cG5[3]*px[99]+cG5[4]*px[132];
        float b = cG5[0]*py[0]+cG5[1]*py[33]+cG5[2]*py[66]+cG5[3]*py[99]+cG5[4]*py[132];
        size_t o = (size_t)z*PLANE + (r0+ty)*WW + (c0+tx);
        J11[o] = a; J22[o] = b;
        // edge_stop(sqrt(x+1e-6)) with P=2,K=20  ==  1/(1+(x+1e-6)/400)
        float gn2 = sqx[(ty+2)*37 + (tx+2)] + sqy[(ty+2)*37 + (tx+2)] + 1e-6f;
        gJ[o] = 1.f/(1.f + gn2*(1.f/400.f));
    }
}

// ---------------------------------------------------------------------------
// K3: paired divergence + loss.  For pred and target in the same tile:
//   g_I  = 1/(1+(J11+J22+1e-6)/400)
//   div_I = sobx(gI*sobx(I)) + soby(gI*soby(I))
//   div_J = sobx(gJ*sobx(J11)) + soby(gJ*soby(J11)) + same for J22
// Accumulates (dI_p-dI_t)^2 + (dJ_p-dJ_t)^2 directly -> no div planes stored.
// tile 32x32, I/J halo 2, flux halo 1.
// ---------------------------------------------------------------------------
__global__ __launch_bounds__(1024) void k_div_loss(const float* __restrict__ Ip,
                                                   const float* __restrict__ It) {
    __shared__ float sI[36*37], sA[36*37], sB[36*37], sG[36*37];
    __shared__ float fx[34*35], fy[34*35];
    const int z  = blockIdx.z;
    const int r0 = blockIdx.y*32, c0 = blockIdx.x*32;
    const int tid = threadIdx.y*32 + threadIdx.x;
    const int ty = threadIdx.y, tx = threadIdx.x;

    float dIp = 0.f, dJp = 0.f, dIt = 0.f, dJt = 0.f;

    for (int t = 0; t < 2; ++t) {
        const float* I = (t ? It     : Ip    ) + (size_t)z*PLANE;
        const float* A = (t ? g_J11t : g_J11p) + (size_t)z*PLANE;
        const float* B = (t ? g_J22t : g_J22p) + (size_t)z*PLANE;
        const float* G = (t ? g_gJt  : g_gJp ) + (size_t)z*PLANE;

        for (int idx = tid; idx < 36*36; idx += 1024) {
            int i = idx/36, j = idx - i*36;
            int gr = r0-2+i, gc = c0-2+j;
            bool in = (unsigned)gr < HH && (unsigned)gc < WW;
            int o = gr*WW + gc;
            sI[i*37+j] = in ? I[o] : 0.f;
            sA[i*37+j] = in ? A[o] : 0.f;
            sB[i*37+j] = in ? B[o] : 0.f;
            sG[i*37+j] = in ? G[o] : 0.f;
        }
        __syncthreads();

        // ---- div_I flux ----
        for (int idx = tid; idx < 34*34; idx += 1024) {
            int i = idx/34, j = idx - i*34;
            int gr = r0-1+i, gc = c0-1+j;
            float vx = 0.f, vy = 0.f;
            if ((unsigned)gr < HH && (unsigned)gc < WW) {
                float gI = 1.f/(1.f + (sA[(i+1)*37+(j+1)] + sB[(i+1)*37+(j+1)] + 1e-6f)*(1.f/400.f));
                vx = gI*sobx(sI, 37, i+1, j+1);
                vy = gI*soby(sI, 37, i+1, j+1);
            }
            fx[i*35+j] = vx; fy[i*35+j] = vy;
        }
        __syncthreads();
        float dI = sobx(fx, 35, ty+1, tx+1) + soby(fy, 35, ty+1, tx+1);
        __syncthreads();

        // ---- div_J flux: J11 ----
        for (int idx = tid; idx < 34*34; idx += 1024) {
            int i = idx/34, j = idx - i*34;
            int gr = r0-1+i, gc = c0-1+j;
            float vx = 0.f, vy = 0.f;
            if ((unsigned)gr < HH && (unsigned)gc < WW) {
                float g = sG[(i+1)*37+(j+1)];
                vx = g*sobx(sA, 37, i+1, j+1);
                vy = g*soby(sA, 37, i+1, j+1);
            }
            fx[i*35+j] = vx; fy[i*35+j] = vy;
        }
        __syncthreads();
        float dJ = sobx(fx, 35, ty+1, tx+1) + soby(fy, 35, ty+1, tx+1);
        __syncthreads();

        // ---- div_J flux: J22 ----
        for (int idx = tid; idx < 34*34; idx += 1024) {
            int i = idx/34, j = idx - i*34;
            int gr = r0-1+i, gc = c0-1+j;
            float vx = 0.f, vy = 0.f;
            if ((unsigned)gr < HH && (unsigned)gc < WW) {
                float g = sG[(i+1)*37+(j+1)];
                vx = g*sobx(sB, 37, i+1, j+1);
                vy = g*soby(sB, 37, i+1, j+1);
            }
            fx[i*35+j] = vx; fy[i*35+j] = vy;
        }
        __syncthreads();
        dJ += sobx(fx, 35, ty+1, tx+1) + soby(fy, 35, ty+1, tx+1);
        __syncthreads();

        if (t == 0) { dIp = dI; dJp = dJ; } else { dIt = dI; dJt = dJ; }
    }

    float ddi = dIp - dIt, ddj = dJp - dJt;
    float s = ddi*ddi + ddj*ddj;

    // block reduce (reuse fx; all prior reads drained by last __syncthreads)
    fx[tid] = s;
    __syncthreads();
    #pragma unroll
    for (int off = 512; off > 0; off >>= 1) {
        if (tid < off) fx[tid] += fx[tid+off];
        __syncthreads();
    }
    if (tid == 0) atomicAdd(&g_acc, (double)fx[0]);
}

// ---------------------------------------------------------------------------
__global__ void k_zero() { g_acc = 0.0; }
__global__ void k_fin(float* __restrict__ out) {
    // loss_I + loss_J = (sum dI^2 + sum dJ^2) / (8*1024*1024)
    out[0] = (float)(g_acc * (1.0/8388608.0));
}

// ---------------------------------------------------------------------------
extern "C" void kernel_launch(void* const* d_in, const int* in_sizes, int n_in,
                              void* d_out, int out_size) {
    (void)in_sizes; (void)n_in; (void)out_size;
    const float* pred = (const float*)d_in[0];
    const float* targ = (const float*)d_in[1];
    float* out = (float*)d_out;

    dim3 blk(32, 32, 1);
    dim3 grd(WW/32, HH/32, NB);

    k_zero<<<1, 1>>>();
    k_gauss7<<<grd, blk>>>(pred);
    k_struct<<<grd, blk>>>(0);
    k_gauss7<<<grd, blk>>>(targ);
    k_struct<<<grd, blk>>>(1);
    k_div_loss<<<grd, blk>>>(pred, targ);
    k_fin<<<1, 1>>>(out);
}

// round 5
// speedup vs baseline: 1.7659x; 1.7659x over previous
#include <cuda_runtime.h>
#include <cstdint>

// Geometry fixed by dataset: 2 inputs of (8,1,1024,1024) fp32.
#define HH 1024
#define WW 1024
#define NB 8
#define PLANE (HH*WW)
#define NTOT (NB*PLANE)

// ---------------------------------------------------------------------------
// Scratch planes: index 0..7 = pred, 8..15 = target
// S = J11+J22 (downstream math only needs the sum — div/conv linearity),
// gJ = edge-stop of |grad I_sigma|.
// ---------------------------------------------------------------------------
static __device__ float g_S[2*NTOT], g_gJ[2*NTOT];
static __device__ double g_acc;

// ---------------------------------------------------------------------------
// Gaussian weights as compile-time immediates
// ---------------------------------------------------------------------------
#define E05f 0.6065306597126334f     /* exp(-0.5) */
#define E20f 0.1353352832366127f     /* exp(-2)   */
#define E45f 0.011108996538242306f   /* exp(-4.5) */
#define E80f 0.00033546262790251185f /* exp(-8)   */

constexpr float G7S = 1.f + 2.f*(E05f + E20f + E45f);
constexpr float G70 = E45f/G7S, G71 = E20f/G7S, G72 = E05f/G7S, G73 = 1.f/G7S;
constexpr float G5S = 1.f + 2.f*(E20f + E80f);
constexpr float G50 = E80f/G5S, G51 = E20f/G5S, G52 = 1.f/G5S;

// ---------------------------------------------------------------------------
// Sobel helpers (cross-correlation, XLA conv semantics)
// SOBEL_X = [[-1,0,1],[-2,0,2],[-1,0,1]]  SOBEL_Y = [[1,2,1],[0,0,0],[-1,-2,-1]]
// ---------------------------------------------------------------------------
__device__ __forceinline__ float sobx(const float* s, int st, int i, int j) {
    const float* a = s + (i-1)*st + j;
    const float* b = s + (i  )*st + j;
    const float* c = s + (i+1)*st + j;
    return (a[1]-a[-1]) + 2.f*(b[1]-b[-1]) + (c[1]-c[-1]);
}
__device__ __forceinline__ float soby(const float* s, int st, int i, int j) {
    const float* a = s + (i-1)*st + j;
    const float* c = s + (i+1)*st + j;
    return (a[-1]+2.f*a[0]+a[1]) - (c[-1]+2.f*c[0]+c[1]);
}

// ---------------------------------------------------------------------------
// k_front: FUSED gauss7 -> sobel -> |grad|^2 -> gauss5 (+ g_for_J).
// Output tile 32x32.  Raw region 44 rows x 48 cols (halo 6, 16B col align).
// gridDim.z = 16 (z<8: pred plane z; z>=8: target plane z-8)
// block = (32,16) = 512 threads.
// NOTE: isg (I_sigma) must be ZERO outside the image — the reference's
// conv2d(I_sigma, SOBEL) zero-pads I_sigma itself.
// ---------------------------------------------------------------------------
__global__ __launch_bounds__(512) void k_front(const float* __restrict__ pred,
                                               const float* __restrict__ targ) {
    __shared__ float raw[44*48];   // rows r0-6.., cols c0-8.. (stride 48)
    __shared__ float hb [44*40];   // h-gauss7, cols c0-3.. (38 used)
    __shared__ float isg[38*40];   // I_sigma, rows r0-3.., cols c0-3..
    __shared__ float sq [36*38];   // Isx^2+Isy^2, rows/cols r0-2..
    __shared__ float h5 [36*33];   // h-gauss5 of sq

    const int z  = blockIdx.z;                 // 0..15
    const int r0 = blockIdx.y*32, c0 = blockIdx.x*32;
    const float* img = (z < NB ? pred : targ) + (size_t)(z & 7)*PLANE;
    const int tid = threadIdx.y*32 + threadIdx.x;
    const bool interior = (blockIdx.x >= 1 && blockIdx.x <= 30 &&
                           blockIdx.y >= 1 && blockIdx.y <= 30);

    // ---- load raw (vectorized on interior) ----
    if (interior) {
        const float4* base = (const float4*)(img + (r0-6)*WW + (c0-8));
        for (int idx = tid; idx < 44*12; idx += 512) {
            int i = idx / 12, j = idx - i*12;
            ((float4*)raw)[i*12 + j] = base[i*(WW/4) + j];
        }
    } else {
        for (int idx = tid; idx < 44*48; idx += 512) {
            int i = idx / 48, j = idx - i*48;
            int gr = r0-6+i, gc = c0-8+j;
            raw[idx] = ((unsigned)gr < HH && (unsigned)gc < WW) ? img[gr*WW+gc] : 0.f;
        }
    }
    __syncthreads();

    // ---- horizontal gauss7: hb(i,j), j=0..37 <- raw(i, j+2..j+8) ----
    for (int idx = tid; idx < 44*38; idx += 512) {
        int i = idx / 38, j = idx - i*38;
        const float* r = raw + i*48 + j + 2;
        hb[i*40+j] = G70*(r[0]+r[6]) + G71*(r[1]+r[5]) + G72*(r[2]+r[4]) + G73*r[3];
    }
    __syncthreads();

    // ---- vertical gauss7: isg(i,j), i=0..37; ZERO outside image ----
    for (int idx = tid; idx < 38*38; idx += 512) {
        int i = idx / 38, j = idx - i*38;
        float v = 0.f;
        if (interior || ((unsigned)(r0-3+i) < HH && (unsigned)(c0-3+j) < WW)) {
            const float* h = hb + i*40 + j;
            v = G70*(h[0]+h[6*40]) + G71*(h[40]+h[5*40])
              + G72*(h[2*40]+h[4*40]) + G73*h[3*40];
        }
        isg[i*40+j] = v;
    }
    __syncthreads();

    // ---- |sobel(I_sigma)|^2, zero outside image: sq on 36x36 ----
    for (int idx = tid; idx < 36*36; idx += 512) {
        int i = idx / 36, j = idx - i*36;
        float v = 0.f;
        if (interior || ((unsigned)(r0-2+i) < HH && (unsigned)(c0-2+j) < WW)) {
            float sx = sobx(isg, 40, i+1, j+1);
            float sy = soby(isg, 40, i+1, j+1);
            v = sx*sx + sy*sy;
        }
        sq[i*38+j] = v;
    }
    __syncthreads();

    // ---- horizontal gauss5: 36x32 ----
    for (int idx = tid; idx < 36*32; idx += 512) {
        int i = idx >> 5, j = idx & 31;
        const float* p = sq + i*38 + j;
        h5[i*33+j] = G50*(p[0]+p[4]) + G51*(p[1]+p[3]) + G52*p[2];
    }
    __syncthreads();

    // ---- vertical gauss5 -> S, plus g_for_J; 32x32 (2 rows/thread) ----
    #pragma unroll
    for (int k = 0; k < 2; ++k) {
        int y = threadIdx.y + k*16, x = threadIdx.x;
        const float* p = h5 + y*33 + x;
        float s = G50*(p[0]+p[4*33]) + G51*(p[33]+p[3*33]) + G52*p[2*33];
        // edge_stop(sqrt(v+1e-6)) with P=2,K=20 == 1/(1 + (v+1e-6)/400)
        float gn2 = sq[(y+2)*38 + x+2] + 1e-6f;
        size_t o = (size_t)z*PLANE + (r0+y)*WW + (c0+x);
        g_S[o]  = s;
        g_gJ[o] = 1.f/(1.f + gn2*(1.f/400.f));
    }
}

// ---------------------------------------------------------------------------
// k_div: paired divergence + loss.
//   gI = 1/(1+(S+1e-6)/400);  div_I = div(gI * grad I)
//   div_J = div(gJ * grad S)   (J11+J22 collapsed by linearity)
// Accumulates (dI_p-dI_t)^2 + (dJ_p-dJ_t)^2 directly.
// block = (32,32) = 1024, grid z = 8.
// ---------------------------------------------------------------------------
__global__ __launch_bounds__(1024) void k_div(const float* __restrict__ Ip,
                                              const float* __restrict__ It) {
    __shared__ float sI[36*40], sS[36*40], sG[36*40]; // rows r0-2.., cols c0-4..
    __shared__ float fxI[34*35], fyI[34*35];
    __shared__ float fxJ[34*35], fyJ[34*35];
    __shared__ float wsum[32];

    const int z  = blockIdx.z;
    const int r0 = blockIdx.y*32, c0 = blockIdx.x*32;
    const int ty = threadIdx.y, tx = threadIdx.x;
    const int tid = ty*32 + tx;
    const bool interior = (blockIdx.x >= 1 && blockIdx.x <= 30 &&
                           blockIdx.y >= 1 && blockIdx.y <= 30);

    float dI_[2], dJ_[2];

    #pragma unroll
    for (int t = 0; t < 2; ++t) {
        const float* I = (t ? It : Ip) + (size_t)z*PLANE;
        const size_t off = (size_t)(t*NB + z)*PLANE;
        const float* S = g_S  + off;
        const float* G = g_gJ + off;

        // ---- load 3 planes with halo (vectorized on interior) ----
        if (interior) {
            const size_t go = (size_t)(r0-2)*WW + (c0-4);
            const float4* bI = (const float4*)(I + go);
            const float4* bS = (const float4*)(S + go);
            const float4* bG = (const float4*)(G + go);
            for (int idx = tid; idx < 36*10; idx += 1024) {
                int i = idx / 10, j = idx - i*10;
                int gofs = i*(WW/4) + j;
                int sofs = i*10 + j;
                ((float4*)sI)[sofs] = bI[gofs];
                ((float4*)sS)[sofs] = bS[gofs];
                ((float4*)sG)[sofs] = bG[gofs];
            }
        } else {
            for (int idx = tid; idx < 36*40; idx += 1024) {
                int i = idx / 40, j = idx - i*40;
                int gr = r0-2+i, gc = c0-4+j;
                bool in = (unsigned)gr < HH && (unsigned)gc < WW;
                int o = gr*WW + gc;
                sI[idx] = in ? I[o] : 0.f;
                sS[idx] = in ? S[o] : 0.f;
                sG[idx] = in ? G[o] : 0.f;
            }
        }
        __syncthreads();

        // ---- 4 flux planes in one pass, 34x34 ----
        for (int idx = tid; idx < 34*34; idx += 1024) {
            int i = idx / 34, j = idx - i*34;
            bool in = interior ||
                      ((unsigned)(r0-1+i) < HH && (unsigned)(c0-1+j) < WW);
            int ci = (i+1)*40 + (j+3);                 // center in s* layout
            float gI = 0.f, g = 0.f;
            if (in) {
                gI = 1.f/(1.f + (sS[ci] + 1e-6f)*(1.f/400.f));
                g  = sG[ci];
            }
            int fo = i*35 + j;
            fxI[fo] = gI*sobx(sI, 40, i+1, j+3);
            fyI[fo] = gI*soby(sI, 40, i+1, j+3);
            fxJ[fo] = g *sobx(sS, 40, i+1, j+3);
            fyJ[fo] = g *soby(sS, 40, i+1, j+3);
        }
        __syncthreads();

        // ---- combine: one output pixel per thread ----
        dI_[t] = sobx(fxI, 35, ty+1, tx+1) + soby(fyI, 35, ty+1, tx+1);
        dJ_[t] = sobx(fxJ, 35, ty+1, tx+1) + soby(fyJ, 35, ty+1, tx+1);
        __syncthreads();   // protect tiles before next t
    }

    float ddi = dI_[0] - dI_[1], ddj = dJ_[0] - dJ_[1];
    float s = ddi*ddi + ddj*ddj;

    // warp-shuffle reduction
    #pragma unroll
    for (int o = 16; o > 0; o >>= 1) s += __shfl_down_sync(0xffffffffu, s, o);
    if ((tid & 31) == 0) wsum[tid >> 5] = s;
    __syncthreads();
    if (tid < 32) {
        float v = wsum[tid];
        #pragma unroll
        for (int o = 16; o > 0; o >>= 1) v += __shfl_down_sync(0xffffffffu, v, o);
        if (tid == 0) atomicAdd(&g_acc, (double)v);
    }
}

// ---------------------------------------------------------------------------
__global__ void k_zero() { g_acc = 0.0; }
__global__ void k_fin(float* __restrict__ out) {
    out[0] = (float)(g_acc * (1.0/8388608.0));   // /(8*1024*1024)
}

// ---------------------------------------------------------------------------
extern "C" void kernel_launch(void* const* d_in, const int* in_sizes, int n_in,
                              void* d_out, int out_size) {
    (void)in_sizes; (void)n_in; (void)out_size;
    const float* pred = (const float*)d_in[0];
    const float* targ = (const float*)d_in[1];
    float* out = (float*)d_out;

    k_zero<<<1, 1>>>();
    k_front<<<dim3(WW/32, HH/32, 16), dim3(32, 16)>>>(pred, targ);
    k_div  <<<dim3(WW/32, HH/32, NB), dim3(32, 32)>>>(pred, targ);
    k_fin<<<1, 1>>>(out);
}